// round 11
// baseline (speedup 1.0000x reference)
#include <cuda_runtime.h>
#include <cstdint>

// Problem constants
#define K_CODES 1024
#define D_DIM   256
#define HW      1024      // 32*32 pixels per image
#define NPIX    65536

// Tiling (conservative: static smem < 48KB, scalar math only)
#define TILE_P  32        // pixels per CTA
#define TILE_K  32        // codes per k-tile
#define NUM_KT  (K_CODES / TILE_K)   // 32
#define CHUNK_D 64
#define NUM_DC  (D_DIM / CHUNK_D)    // 4

#define ZS_STR  258       // 256 + 2 pad: conflict-free
#define ES_STR  66        // 64 + 2 pad:  conflict-free

__device__ float g_norme[K_CODES];

// Monotone float -> uint mapping; pack with index so u64-min == (score, then lowest index)
__device__ __forceinline__ unsigned long long pack_score(float s, int k) {
    unsigned u = __float_as_uint(s);
    u = ((int)u < 0) ? ~u : (u | 0x80000000u);
    return ((unsigned long long)u << 32) | (unsigned)k;
}

__device__ __forceinline__ unsigned long long umin64(unsigned long long a,
                                                     unsigned long long b) {
    return a < b ? a : b;
}

// ---------------- kernels ----------------

__global__ void norme_kernel(const float* __restrict__ emb) {
    int k = blockIdx.x * blockDim.x + threadIdx.x;
    if (k >= K_CODES) return;
    const float* row = emb + (size_t)k * D_DIM;
    float a = 0.0f;
#pragma unroll 8
    for (int d = 0; d < D_DIM; d++) a = fmaf(row[d], row[d], a);
    g_norme[k] = a;
}

__global__ void __launch_bounds__(256)
vq_argmin_kernel(const float* __restrict__ z,
                 const float* __restrict__ emb,
                 float* __restrict__ out) {
    __shared__ float zs[TILE_P * ZS_STR];                 // 33024 B
    __shared__ float es[TILE_K * ES_STR];                 //  8448 B
    __shared__ unsigned long long red[TILE_P * 16];       //  4096 B
    __shared__ float nz[TILE_P];                          //   128 B

    const int tid = threadIdx.x;
    const int pg  = blockIdx.x * TILE_P;   // global flattened pixel base (b*HW + p0)
    const int b   = pg >> 10;              // image (HW=1024: tiles never cross images)
    const int p0  = pg & 1023;

    const float* zb = z + (size_t)b * D_DIM * HW + p0;

    // ---- load z tile (transposed): zs[p][d] = z[b][d][p0+p]; lanes = p -> coalesced ----
    {
        const int p  = tid & 31;
        const int dg = tid >> 5;           // 0..7
#pragma unroll 4
        for (int r = 0; r < 32; r++) {
            const int d = dg * 32 + r;
            zs[p * ZS_STR + d] = zb[(size_t)d * HW + p];
        }
    }
    __syncthreads();

    // ---- per-pixel ||z||^2 (uniform shift per pixel; kept for score fidelity) ----
    if (tid < TILE_P) {
        float a = 0.0f;
        const float* row = zs + tid * ZS_STR;
#pragma unroll 8
        for (int d = 0; d < D_DIM; d++) a = fmaf(row[d], row[d], a);
        nz[tid] = a;
    }

    const int tx = tid & 15;   // code slot: codes {tx, tx+16} of the k-tile
    const int ty = tid >> 4;   // pixel slot: pixels {ty, ty+16}

    unsigned long long bestp = ~0ull;   // consumed in tid < 32

    for (int kt = 0; kt < NUM_KT; kt++) {
        float a00 = 0.f, a01 = 0.f, a10 = 0.f, a11 = 0.f;

        for (int dc = 0; dc < NUM_DC; dc++) {
            __syncthreads();   // prior phase readers done (also guards red[] reuse)

            // load es: 32 codes x 64 floats of this d-chunk (coalesced 8-float runs)
            {
                const int row = tid >> 3;          // 0..31
                const int fo  = (tid & 7) * 8;     // 0..56
                const float* src = emb + (size_t)(kt * TILE_K + row) * D_DIM
                                       + dc * CHUNK_D + fo;
                float* dst = es + row * ES_STR + fo;
#pragma unroll
                for (int i = 0; i < 8; i++) dst[i] = src[i];
            }
            __syncthreads();

            const float* zr0 = zs + ty * ZS_STR + dc * CHUNK_D;
            const float* zr1 = zs + (ty + 16) * ZS_STR + dc * CHUNK_D;
            const float* er0 = es + tx * ES_STR;
            const float* er1 = es + (tx + 16) * ES_STR;

#pragma unroll 8
            for (int d = 0; d < CHUNK_D; d++) {
                const float za  = zr0[d];
                const float zb2 = zr1[d];
                const float ea  = er0[d];
                const float eb2 = er1[d];
                a00 = fmaf(za,  ea,  a00);
                a01 = fmaf(za,  eb2, a01);
                a10 = fmaf(zb2, ea,  a10);
                a11 = fmaf(zb2, eb2, a11);
            }
        }

        // ---- fold k-tile argmin ----
        {
            const int c0 = kt * TILE_K + tx;
            const int c1 = c0 + 16;
            const float ne0 = g_norme[c0];
            const float ne1 = g_norme[c1];

            // pixel ty: reference rounding (||z||^2 - 2*(z.e)) + ||e||^2, no contraction
            {
                const float nzp = nz[ty];
                const float s0 = __fadd_rn(__fsub_rn(nzp, __fmul_rn(2.0f, a00)), ne0);
                const float s1 = __fadd_rn(__fsub_rn(nzp, __fmul_rn(2.0f, a01)), ne1);
                red[ty * 16 + tx] = umin64(pack_score(s0, c0), pack_score(s1, c1));
            }
            // pixel ty+16
            {
                const float nzp = nz[ty + 16];
                const float s0 = __fadd_rn(__fsub_rn(nzp, __fmul_rn(2.0f, a10)), ne0);
                const float s1 = __fadd_rn(__fsub_rn(nzp, __fmul_rn(2.0f, a11)), ne1);
                red[(ty + 16) * 16 + tx] = umin64(pack_score(s0, c0), pack_score(s1, c1));
            }
        }
        __syncthreads();

        if (tid < TILE_P) {
            unsigned long long m = red[tid * 16];
#pragma unroll
            for (int x = 1; x < 16; x++) m = umin64(m, red[tid * 16 + x]);
            bestp = umin64(bestp, m);
        }
        // next iteration's first __syncthreads orders red[]/es[] reuse
    }

    // *** KEY CHANGE vs Round 6: output dtype is float32 per __output__ ***
    // (indices 0..1023 are exactly representable; previous int32 bit-pattern
    //  writes reinterpret as denormals ~1e-43 -> rel_err == 1.0 exactly,
    //  matching every observed failure)
    if (tid < TILE_P)
        out[blockIdx.x * TILE_P + tid] = (float)(int)(bestp & 0xFFFFFFFFull);
}

// ---------------- launch ----------------

extern "C" void kernel_launch(void* const* d_in, const int* in_sizes, int n_in,
                              void* d_out, int out_size) {
    // Dispatch inputs BY SIZE — robust to metadata ordering.
    // z_e_x: 64*256*32*32 = 16777216 elems; emb: 1024*256 = 262144 elems.
    const float* z   = (const float*)d_in[0];
    const float* emb = (const float*)d_in[1];
    if (n_in >= 2 && in_sizes[0] == K_CODES * D_DIM) {
        emb = (const float*)d_in[0];
        z   = (const float*)d_in[1];
    }
    float* out = (float*)d_out;   // [64,32,32] indices as float32

    norme_kernel<<<(K_CODES + 255) / 256, 256>>>(emb);
    vq_argmin_kernel<<<NPIX / TILE_P, 256>>>(z, emb, out);
}

// round 15
// speedup vs baseline: 2.5501x; 2.5501x over previous
#include <cuda_runtime.h>
#include <cstdint>

// Problem constants
#define K_CODES 1024
#define D_DIM   256
#define HW      1024      // 32*32 pixels per image
#define NPIX    65536

// Tiling
#define TILE_P     64     // pixels per CTA
#define TILE_K     128    // codes per k-tile
#define CHUNK_D    64     // d per e-chunk
#define NUM_KT     (K_CODES / TILE_K)            // 8
#define CHUNKS_PER_KT (D_DIM / CHUNK_D)          // 4
#define TOTAL_CHUNKS  (NUM_KT * CHUNKS_PER_KT)   // 32

#define ZS_STRIDE  260    // 256 + 4 pad (16B-aligned rows, conflict-breaking)
#define ES_STRIDE  68     // 64 + 4 pad

// smem byte offsets
#define SM_ZS    0
#define SM_ZS_SZ (TILE_P * ZS_STRIDE * 4)                 // 66560
#define SM_ES0   (SM_ZS + SM_ZS_SZ)                       // 66560
#define SM_ES_SZ (TILE_K * ES_STRIDE * 4)                 // 34816
#define SM_ES1   (SM_ES0 + SM_ES_SZ)                      // 101376
#define SM_RED   (SM_ES1 + SM_ES_SZ)                      // 136192
#define SM_RED_SZ (TILE_P * 16 * 8)                       // 8192
#define SM_NZ    (SM_RED + SM_RED_SZ)                     // 144384
#define SM_TOTAL (SM_NZ + TILE_P * 4)                     // 144640

__device__ float g_norme[K_CODES];

// ---------------- helpers ----------------

__device__ __forceinline__ unsigned long long ffma2(unsigned long long a,
                                                    unsigned long long b,
                                                    unsigned long long c) {
    unsigned long long d;
    asm("fma.rn.f32x2 %0, %1, %2, %3;" : "=l"(d) : "l"(a), "l"(b), "l"(c));
    return d;
}

__device__ __forceinline__ void cp_async16(uint32_t smem_addr, const float* gptr) {
    asm volatile("cp.async.cg.shared.global [%0], [%1], 16;\n"
                 :: "r"(smem_addr), "l"(gptr));
}
__device__ __forceinline__ void cp_commit() {
    asm volatile("cp.async.commit_group;\n");
}
template <int N>
__device__ __forceinline__ void cp_wait() {
    asm volatile("cp.async.wait_group %0;\n" :: "n"(N));
}

// Monotone float -> uint mapping; pack with index so u64-min == (score, then lowest index)
__device__ __forceinline__ unsigned long long pack_score(float s, int k) {
    unsigned u = __float_as_uint(s);
    u = ((int)u < 0) ? ~u : (u | 0x80000000u);
    return ((unsigned long long)u << 32) | (unsigned)k;
}

__device__ __forceinline__ unsigned long long umin64(unsigned long long a,
                                                     unsigned long long b) {
    return a < b ? a : b;
}

// ---------------- kernels ----------------

__global__ void norme_kernel(const float* __restrict__ emb) {
    int k = blockIdx.x * blockDim.x + threadIdx.x;
    if (k >= K_CODES) return;
    const float4* row = reinterpret_cast<const float4*>(emb + (size_t)k * D_DIM);
    float4 a = make_float4(0.f, 0.f, 0.f, 0.f);
#pragma unroll
    for (int i = 0; i < D_DIM / 4; i++) {
        float4 v = row[i];
        a.x = fmaf(v.x, v.x, a.x);
        a.y = fmaf(v.y, v.y, a.y);
        a.z = fmaf(v.z, v.z, a.z);
        a.w = fmaf(v.w, v.w, a.w);
    }
    g_norme[k] = (a.x + a.y) + (a.z + a.w);
}

__global__ void __launch_bounds__(256, 1)
vq_argmin_kernel(const float* __restrict__ z,
                 const float* __restrict__ emb,
                 float* __restrict__ out) {
    extern __shared__ char smem[];
    float* zs  = reinterpret_cast<float*>(smem + SM_ZS);    // [64][260]
    float* es0 = reinterpret_cast<float*>(smem + SM_ES0);   // [128][68]
    float* es1 = reinterpret_cast<float*>(smem + SM_ES1);
    unsigned long long* red = reinterpret_cast<unsigned long long*>(smem + SM_RED); // [64][16]
    float* nz  = reinterpret_cast<float*>(smem + SM_NZ);    // [64]

    const int tid  = threadIdx.x;
    const int tile = blockIdx.x;
    const int b    = tile >> 4;            // image index (16 tiles per image)
    const int p0   = (tile & 15) << 6;

    const float* zb = z + (size_t)b * D_DIM * HW + p0;

    // ---- load z tile into smem transposed: zs[p][d] = z[b][d][p0+p] ----
    {
        int p  = tid & 63;
        int dg = tid >> 6;   // 0..3
#pragma unroll
        for (int r = 0; r < 64; r++) {
            int d = r * 4 + dg;
            zs[p * ZS_STRIDE + d] = zb[(size_t)d * HW + p];
        }
    }
    __syncthreads();

    // ---- per-pixel ||z||^2 (uniform per-pixel shift; kept for score fidelity) ----
    if (tid < 64) {
        const float4* row = reinterpret_cast<const float4*>(zs + tid * ZS_STRIDE);
        float4 a = make_float4(0.f, 0.f, 0.f, 0.f);
#pragma unroll
        for (int i = 0; i < D_DIM / 4; i++) {
            float4 v = row[i];
            a.x = fmaf(v.x, v.x, a.x);
            a.y = fmaf(v.y, v.y, a.y);
            a.z = fmaf(v.z, v.z, a.z);
            a.w = fmaf(v.w, v.w, a.w);
        }
        nz[tid] = (a.x + a.y) + (a.z + a.w);
    }

    const int tx = tid & 15;   // code group (codes tx, tx+16, ..., tx+112 of k-tile)
    const int ty = tid >> 4;   // pixel group (pixels 4*ty .. 4*ty+3)

    // e-chunk async loader: chunk c -> (kt = c>>2, dc = c&3); 128 codes x 64 floats
    auto issue_chunk = [&](int c, float* dst_base) {
        int kt = c >> 2, dc = c & 3;
        int lc = tid >> 1, half = tid & 1;
        const float* src = emb + (size_t)((kt << 7) + lc) * D_DIM + (dc << 6) + (half << 5);
        float* dst = dst_base + lc * ES_STRIDE + (half << 5);
        uint32_t saddr = (uint32_t)__cvta_generic_to_shared(dst);
#pragma unroll
        for (int j = 0; j < 8; j++) cp_async16(saddr + j * 16, src + j * 4);
        cp_commit();
    };

    unsigned long long acc[8][4];
    unsigned long long bestp = ~0ull;

    issue_chunk(0, es0);

    for (int c = 0; c < TOTAL_CHUNKS; c++) {
        // chunk c was issued last iteration (or just above for c=0)
        cp_wait<0>();
        __syncthreads();   // (a) chunk c visible to all warps
                           // (b) all warps done reading the buffer we refill next

        if (c + 1 < TOTAL_CHUNKS)
            issue_chunk(c + 1, ((c + 1) & 1) ? es1 : es0);   // overlaps compute below

        const float* eb = (c & 1) ? es1 : es0;

        if ((c & 3) == 0) {
#pragma unroll
            for (int i = 0; i < 8; i++)
#pragma unroll
                for (int j = 0; j < 4; j++) acc[i][j] = 0ull;
        }

        const int dbase = (c & 3) << 6;

#pragma unroll 4
        for (int s = 0; s < 16; s++) {
            const int d = dbase + (s << 2);

            ulonglong2 zf[4];
#pragma unroll
            for (int j = 0; j < 4; j++)
                zf[j] = *reinterpret_cast<const ulonglong2*>(
                    zs + (ty * 4 + j) * ZS_STRIDE + d);

            ulonglong2 ef[8];
#pragma unroll
            for (int i = 0; i < 8; i++)
                ef[i] = *reinterpret_cast<const ulonglong2*>(
                    eb + (i * 16 + tx) * ES_STRIDE + (s << 2));

#pragma unroll
            for (int i = 0; i < 8; i++)
#pragma unroll
                for (int j = 0; j < 4; j++)
                    acc[i][j] = ffma2(zf[j].x, ef[i].x, acc[i][j]);
#pragma unroll
            for (int i = 0; i < 8; i++)
#pragma unroll
                for (int j = 0; j < 4; j++)
                    acc[i][j] = ffma2(zf[j].y, ef[i].y, acc[i][j]);
        }

        if ((c & 3) == 3) {   // k-tile complete: fold argmin
            const int kt = c >> 2;
#pragma unroll
            for (int j = 0; j < 4; j++) {
                const int p = ty * 4 + j;
                const float nzp = nz[p];
                unsigned long long bj = ~0ull;
#pragma unroll
                for (int i = 0; i < 8; i++) {
                    float lo = __uint_as_float((unsigned)(acc[i][j] & 0xFFFFFFFFull));
                    float hi = __uint_as_float((unsigned)(acc[i][j] >> 32));
                    float dot = __fadd_rn(lo, hi);
                    // reference rounding: (||z||^2 - 2*(z.e)) + ||e||^2, no contraction
                    float t  = __fsub_rn(nzp, __fmul_rn(2.0f, dot));
                    int code = (kt << 7) + i * 16 + tx;
                    float sc = __fadd_rn(t, g_norme[code]);
                    bj = umin64(bj, pack_score(sc, code));
                }
                red[p * 16 + tx] = bj;
            }
            __syncthreads();
            if (tid < 64) {
                unsigned long long m = red[tid * 16];
#pragma unroll
                for (int x = 1; x < 16; x++) m = umin64(m, red[tid * 16 + x]);
                bestp = umin64(bestp, m);
            }
            // next loop-top __syncthreads orders red[] reuse
        }
    }

    // output dtype is float32 (indices 0..1023 exactly representable)
    if (tid < 64)
        out[tile * 64 + tid] = (float)(int)(bestp & 0xFFFFFFFFull);
}

// ---------------- launch ----------------

extern "C" void kernel_launch(void* const* d_in, const int* in_sizes, int n_in,
                              void* d_out, int out_size) {
    // Dispatch inputs BY SIZE — robust to metadata ordering.
    const float* z   = (const float*)d_in[0];
    const float* emb = (const float*)d_in[1];
    if (n_in >= 2 && in_sizes[0] == K_CODES * D_DIM) {
        emb = (const float*)d_in[0];
        z   = (const float*)d_in[1];
    }
    float* out = (float*)d_out;   // [64,32,32] indices as float32

    cudaFuncSetAttribute(vq_argmin_kernel,
                         cudaFuncAttributeMaxDynamicSharedMemorySize, SM_TOTAL);

    norme_kernel<<<(K_CODES + 255) / 256, 256>>>(emb);
    vq_argmin_kernel<<<NPIX / TILE_P, 256, SM_TOTAL>>>(z, emb, out);
}

// round 16
// speedup vs baseline: 4.9997x; 1.9606x over previous
#include <cuda_runtime.h>
#include <cstdint>

// Problem constants
#define K_CODES 1024
#define D_DIM   256
#define HW      1024      // 32*32 pixels per image
#define NPIX    65536

// Tiling: TILE_P=64 pixels/CTA, TILE_K=64 codes per k-tile, CHUNK_D=64
#define TILE_P     64
#define TILE_K     64
#define CHUNK_D    64
#define NUM_KT     (K_CODES / TILE_K)            // 16
#define CHUNKS_PER_KT (D_DIM / CHUNK_D)          // 4
#define TOTAL_CHUNKS  (NUM_KT * CHUNKS_PER_KT)   // 64

#define ZS_STRIDE  260    // 256 + 4 pad (16B-aligned rows)
#define ES_STRIDE  68     // 64 + 4 pad (16B-aligned; even wavefront spread)

// smem byte offsets (per CTA: 109,824 B -> 2 CTAs/SM)
#define SM_ZS    0
#define SM_ZS_SZ (TILE_P * ZS_STRIDE * 4)                 // 66560
#define SM_ES0   (SM_ZS + SM_ZS_SZ)
#define SM_ES_SZ (TILE_K * ES_STRIDE * 4)                 // 17408
#define SM_ES1   (SM_ES0 + SM_ES_SZ)
#define SM_RED   (SM_ES1 + SM_ES_SZ)                      // 101376
#define SM_RED_SZ (TILE_P * 16 * 8)                       // 8192
#define SM_NZ    (SM_RED + SM_RED_SZ)                     // 109568
#define SM_TOTAL (SM_NZ + TILE_P * 4)                     // 109824

__device__ float g_norme[K_CODES];

// ---------------- helpers ----------------

__device__ __forceinline__ unsigned long long ffma2(unsigned long long a,
                                                    unsigned long long b,
                                                    unsigned long long c) {
    unsigned long long d;
    asm("fma.rn.f32x2 %0, %1, %2, %3;" : "=l"(d) : "l"(a), "l"(b), "l"(c));
    return d;
}

__device__ __forceinline__ void cp_async16(uint32_t smem_addr, const float* gptr) {
    asm volatile("cp.async.cg.shared.global [%0], [%1], 16;\n"
                 :: "r"(smem_addr), "l"(gptr));
}
__device__ __forceinline__ void cp_commit() {
    asm volatile("cp.async.commit_group;\n");
}
template <int N>
__device__ __forceinline__ void cp_wait() {
    asm volatile("cp.async.wait_group %0;\n" :: "n"(N));
}

// Monotone float -> uint mapping; pack with index so u64-min == (score, then lowest index)
__device__ __forceinline__ unsigned long long pack_score(float s, int k) {
    unsigned u = __float_as_uint(s);
    u = ((int)u < 0) ? ~u : (u | 0x80000000u);
    return ((unsigned long long)u << 32) | (unsigned)k;
}

__device__ __forceinline__ unsigned long long umin64(unsigned long long a,
                                                     unsigned long long b) {
    return a < b ? a : b;
}

// ---------------- kernels ----------------

__global__ void norme_kernel(const float* __restrict__ emb) {
    int k = blockIdx.x * blockDim.x + threadIdx.x;
    if (k >= K_CODES) return;
    const float4* row = reinterpret_cast<const float4*>(emb + (size_t)k * D_DIM);
    float4 a = make_float4(0.f, 0.f, 0.f, 0.f);
#pragma unroll
    for (int i = 0; i < D_DIM / 4; i++) {
        float4 v = row[i];
        a.x = fmaf(v.x, v.x, a.x);
        a.y = fmaf(v.y, v.y, a.y);
        a.z = fmaf(v.z, v.z, a.z);
        a.w = fmaf(v.w, v.w, a.w);
    }
    g_norme[k] = (a.x + a.y) + (a.z + a.w);
}

__global__ void __launch_bounds__(256, 2)
vq_argmin_kernel(const float* __restrict__ z,
                 const float* __restrict__ emb,
                 float* __restrict__ out) {
    extern __shared__ char smem[];
    float* zs  = reinterpret_cast<float*>(smem + SM_ZS);    // [64][260]
    float* es0 = reinterpret_cast<float*>(smem + SM_ES0);   // [64][68]
    float* es1 = reinterpret_cast<float*>(smem + SM_ES1);
    unsigned long long* red = reinterpret_cast<unsigned long long*>(smem + SM_RED); // [64][16]
    float* nz  = reinterpret_cast<float*>(smem + SM_NZ);    // [64]

    const int tid  = threadIdx.x;
    const int tile = blockIdx.x;
    const int b    = tile >> 4;            // image index (16 tiles per image)
    const int p0   = (tile & 15) << 6;

    const float* zb = z + (size_t)b * D_DIM * HW + p0;

    // ---- load z tile transposed: zs[p][d] = z[b][d][p0+p] ----
    {
        int p  = tid & 63;
        int dg = tid >> 6;   // 0..3
#pragma unroll
        for (int r = 0; r < 64; r++) {
            int d = r * 4 + dg;
            zs[p * ZS_STRIDE + d] = zb[(size_t)d * HW + p];
        }
    }
    __syncthreads();

    // ---- per-pixel ||z||^2 ----
    if (tid < 64) {
        const float4* row = reinterpret_cast<const float4*>(zs + tid * ZS_STRIDE);
        float4 a = make_float4(0.f, 0.f, 0.f, 0.f);
#pragma unroll
        for (int i = 0; i < D_DIM / 4; i++) {
            float4 v = row[i];
            a.x = fmaf(v.x, v.x, a.x);
            a.y = fmaf(v.y, v.y, a.y);
            a.z = fmaf(v.z, v.z, a.z);
            a.w = fmaf(v.w, v.w, a.w);
        }
        nz[tid] = (a.x + a.y) + (a.z + a.w);
    }

    const int tx = tid & 15;   // code group: codes {tx, tx+16, tx+32, tx+48} of k-tile
    const int ty = tid >> 4;   // pixel group: pixels 4*ty .. 4*ty+3

    // e-chunk loader: chunk c -> (kt = c>>2, dc = c&3); 64 codes x 64 floats = 16KB
    auto issue_chunk = [&](int c, float* dst_base) {
        const int kt = c >> 2, dc = c & 3;
        const int lane16 = tid & 15;        // 16B column within row
        const int row0   = tid >> 4;        // 0..15
        const float* src0 = emb + (size_t)((kt << 6) + row0) * D_DIM + (dc << 6) + (lane16 << 2);
        float* dst0 = dst_base + row0 * ES_STRIDE + (lane16 << 2);
#pragma unroll
        for (int r = 0; r < 4; r++) {
            uint32_t saddr = (uint32_t)__cvta_generic_to_shared(dst0 + r * 16 * ES_STRIDE);
            cp_async16(saddr, src0 + (size_t)r * 16 * D_DIM);
        }
        cp_commit();
    };

    unsigned long long acc[4][4];          // [code i][pixel j]
    unsigned long long best[4] = {~0ull, ~0ull, ~0ull, ~0ull};   // per pixel j

    issue_chunk(0, es0);

    for (int c = 0; c < TOTAL_CHUNKS; c++) {
        cp_wait<0>();
        __syncthreads();   // chunk c visible; all warps done with buffer being refilled

        if (c + 1 < TOTAL_CHUNKS)
            issue_chunk(c + 1, ((c + 1) & 1) ? es1 : es0);   // overlaps compute below

        const float* eb = (c & 1) ? es1 : es0;

        if ((c & 3) == 0) {
#pragma unroll
            for (int i = 0; i < 4; i++)
#pragma unroll
                for (int j = 0; j < 4; j++) acc[i][j] = 0ull;
        }

        const int dbase = (c & 3) << 6;

#pragma unroll 4
        for (int s = 0; s < 16; s++) {
            const int d = dbase + (s << 2);

            ulonglong2 zf[4];
#pragma unroll
            for (int j = 0; j < 4; j++)
                zf[j] = *reinterpret_cast<const ulonglong2*>(
                    zs + (ty * 4 + j) * ZS_STRIDE + d);

            ulonglong2 ef[4];
#pragma unroll
            for (int i = 0; i < 4; i++)
                ef[i] = *reinterpret_cast<const ulonglong2*>(
                    eb + (i * 16 + tx) * ES_STRIDE + (s << 2));

#pragma unroll
            for (int i = 0; i < 4; i++)
#pragma unroll
                for (int j = 0; j < 4; j++)
                    acc[i][j] = ffma2(zf[j].x, ef[i].x, acc[i][j]);
#pragma unroll
            for (int i = 0; i < 4; i++)
#pragma unroll
                for (int j = 0; j < 4; j++)
                    acc[i][j] = ffma2(zf[j].y, ef[i].y, acc[i][j]);
        }

        if ((c & 3) == 3) {   // k-tile complete: fold argmin IN REGISTERS (no barrier)
            const int kt = c >> 2;
#pragma unroll
            for (int j = 0; j < 4; j++) {
                const float nzp = nz[ty * 4 + j];
#pragma unroll
                for (int i = 0; i < 4; i++) {
                    float lo = __uint_as_float((unsigned)(acc[i][j] & 0xFFFFFFFFull));
                    float hi = __uint_as_float((unsigned)(acc[i][j] >> 32));
                    float dot = __fadd_rn(lo, hi);
                    // reference rounding: (||z||^2 - 2*(z.e)) + ||e||^2, no contraction
                    float t  = __fsub_rn(nzp, __fmul_rn(2.0f, dot));
                    int code = (kt << 6) + i * 16 + tx;
                    float sc = __fadd_rn(t, g_norme[code]);
                    best[j] = umin64(best[j], pack_score(sc, code));
                }
            }
        }
    }

    // ---- single final cross-thread reduction ----
#pragma unroll
    for (int j = 0; j < 4; j++)
        red[(ty * 4 + j) * 16 + tx] = best[j];
    __syncthreads();

    if (tid < 64) {
        unsigned long long m = red[tid * 16];
#pragma unroll
        for (int x = 1; x < 16; x++) m = umin64(m, red[tid * 16 + x]);
        out[tile * 64 + tid] = (float)(int)(m & 0xFFFFFFFFull);   // float32 output
    }
}

// ---------------- launch ----------------

extern "C" void kernel_launch(void* const* d_in, const int* in_sizes, int n_in,
                              void* d_out, int out_size) {
    // Dispatch inputs BY SIZE — robust to metadata ordering.
    const float* z   = (const float*)d_in[0];
    const float* emb = (const float*)d_in[1];
    if (n_in >= 2 && in_sizes[0] == K_CODES * D_DIM) {
        emb = (const float*)d_in[0];
        z   = (const float*)d_in[1];
    }
    float* out = (float*)d_out;   // [64,32,32] indices as float32

    cudaFuncSetAttribute(vq_argmin_kernel,
                         cudaFuncAttributeMaxDynamicSharedMemorySize, SM_TOTAL);

    norme_kernel<<<(K_CODES + 255) / 256, 256>>>(emb);
    vq_argmin_kernel<<<NPIX / TILE_P, 256, SM_TOTAL>>>(z, emb, out);
}